// round 1
// baseline (speedup 1.0000x reference)
#include <cuda_runtime.h>
#include <math.h>

// ---------------- problem constants ----------------
#define BATCHN   256
#define SEQ      257
#define HID      128
#define NPATCH   256      // 16*16
#define INPUT_D  588      // 3*14*14
#define KPAD     592      // 588 padded to multiple of 8 (and 16B)
#define FF       512
#define OUTD     1000
#define NH       2
#define DH       64
#define ROWS     (BATCHN*SEQ)     // 65792 = 514*128
#define TROWS    (BATCHN*NPATCH)  // 65536 = 512*128
#define SCALE_ATT 0.125f          // 1/sqrt(64)

// ---------------- scratch (static device globals; no allocs) ----------------
__device__ float g_X0[TROWS * KPAD];          // gathered patches, K padded
__device__ float g_mapWp[HID * KPAD];         // padded patch-embed weight
__device__ float g_out[ROWS * HID];           // residual stream
__device__ float g_x[ROWS * HID];             // LN output
__device__ float g_qkv[ROWS * 384];           // q|k|v concatenated (heads packed)
__device__ float g_attn[512 * SEQ * SEQ];     // per (b,h) score/attn matrices
__device__ float g_mlp[ROWS * FF];            // MLP hidden
__device__ float g_logits[BATCHN * OUTD];     // head logits
__device__ float g_pos[SEQ * HID];            // positional embedding
__device__ float g_wqkv[384 * HID];           // block-diagonal fused qkv weight
__device__ float g_bqkv[384];                 // fused qkv bias

// ---------------- positional embedding (double precision like numpy) -------
__global__ void pos_kernel() {
    int idx = blockIdx.x * blockDim.x + threadIdx.x;
    if (idx >= SEQ * HID) return;
    int s = idx / HID, j = idx % HID;
    double e = (double)((j & 1) ? (j - 1) : j) / 128.0;
    double freq = pow(10000.0, e);
    double arg = (double)s / freq;
    g_pos[idx] = (float)((j & 1) ? cos(arg) : sin(arg));
}

// ---------------- patch gather: images -> X0 [TROWS][KPAD] -----------------
__global__ void gather_kernel(const float* __restrict__ images) {
    int idx = blockIdx.x * blockDim.x + threadIdx.x;  // < TROWS*KPAD
    int r = idx / KPAD, k = idx - r * KPAD;
    float v = 0.f;
    if (k < INPUT_D) {
        int b = r >> 8, p = r & 255;
        int py = p >> 4, px = p & 15;
        int c = k / 196, rem = k - c * 196;
        int iy = rem / 14, ix = rem - iy * 14;
        v = images[((size_t)(b * 3 + c) * 224 + (py * 14 + iy)) * 224 + (px * 14 + ix)];
    }
    g_X0[idx] = v;
}

// ---------------- pad mapW to KPAD ----------------
__global__ void padw_kernel(const float* __restrict__ mapW) {
    int idx = blockIdx.x * blockDim.x + threadIdx.x;
    if (idx >= HID * KPAD) return;
    int r = idx / KPAD, c = idx - r * KPAD;
    g_mapWp[idx] = (c < INPUT_D) ? mapW[r * INPUT_D + c] : 0.f;
}

// ---------------- cls token + POS[0] into row b*257 ----------------
__global__ void cls_kernel(const float* __restrict__ cls) {
    int idx = blockIdx.x * blockDim.x + threadIdx.x;
    if (idx >= BATCHN * HID) return;
    int b = idx >> 7, n = idx & 127;
    g_out[(size_t)b * SEQ * HID + n] = cls[n] + g_pos[n];
}

// ---------------- fused qkv weight build (block-diagonal) ----------------
__global__ void build_wqkv_kernel(int blk,
                                  const float* __restrict__ qW, const float* __restrict__ qb,
                                  const float* __restrict__ kW, const float* __restrict__ kb,
                                  const float* __restrict__ vW, const float* __restrict__ vb) {
    int idx = blockIdx.x * blockDim.x + threadIdx.x;
    if (idx >= 384 * HID) return;
    int r = idx >> 7, c = idx & 127;
    int mat = r >> 7;          // 0=q 1=k 2=v
    int rr = r & 127;
    int hr = rr >> 6, e = rr & 63;
    int ch = c >> 6, d = c & 63;
    const float* W = (mat == 0) ? qW : (mat == 1) ? kW : vW;
    float val = (ch == hr) ? W[(((blk * NH + hr) * DH) + e) * DH + d] : 0.f;
    g_wqkv[idx] = val;
    if (c == 0) {
        const float* B = (mat == 0) ? qb : (mat == 1) ? kb : vb;
        g_bqkv[r] = B[(blk * NH + hr) * DH + e];
    }
}

// ---------------- layernorm: one warp per 128-wide row ----------------
__global__ void ln_kernel(const float* __restrict__ src, float* __restrict__ dst,
                          const float* __restrict__ g, const float* __restrict__ bb) {
    int warp = threadIdx.x >> 5, lane = threadIdx.x & 31;
    int row = blockIdx.x * 8 + warp;
    if (row >= ROWS) return;
    float4 v = *(const float4*)(src + (size_t)row * HID + lane * 4);
    float s = v.x + v.y + v.z + v.w;
    #pragma unroll
    for (int o = 16; o; o >>= 1) s += __shfl_xor_sync(0xffffffffu, s, o);
    float mu = s * (1.0f / 128.0f);
    float dx = v.x - mu, dy = v.y - mu, dz = v.z - mu, dw = v.w - mu;
    float q = dx * dx + dy * dy + dz * dz + dw * dw;
    #pragma unroll
    for (int o = 16; o; o >>= 1) q += __shfl_xor_sync(0xffffffffu, q, o);
    float rs = rsqrtf(q * (1.0f / 128.0f) + 1e-5f);
    int n = lane * 4;
    float4 go = *(const float4*)(g + n);
    float4 bo = *(const float4*)(bb + n);
    float4 r;
    r.x = dx * rs * go.x + bo.x;
    r.y = dy * rs * go.y + bo.y;
    r.z = dz * rs * go.z + bo.z;
    r.w = dw * rs * go.w + bo.w;
    *(float4*)(dst + (size_t)row * HID + n) = r;
}

// ---------------- generic tiled SGEMM: C = A[M,K] @ B[N,K]^T + epilogue ----
// MODE 0: C[m*ldc+n] = acc + bias[n]
// MODE 1: token scatter: row m -> (b=m>>8, s=(m&255)+1); C[(b*257+s)*128+n] = acc+bias[n]+pos[s*128+n]
// MODE 2: gelu(acc+bias[n])  (exact erf)
// MODE 3: C[m*ldc+n] += acc + bias[n]  (residual accumulate)
// MODE 4: plain store (same as 0)
template <int MODE>
__global__ void __launch_bounds__(256) sgemm_kernel(
    const float* __restrict__ A, int lda,
    const float* __restrict__ B, int ldb,
    float* __restrict__ C, int ldc,
    int M, int N, int K,
    const float* __restrict__ bias, const float* __restrict__ extra) {
    __shared__ __align__(16) float As[8][128];
    __shared__ __align__(16) float Bs[8][128];
    int t = threadIdx.x;
    int n0 = blockIdx.x * 128;
    int m0 = blockIdx.y * 128;
    int arow = t >> 1;
    int ak = (t & 1) * 4;
    int tm = (t >> 4) << 3;
    int tn = (t & 15) << 3;
    float acc[8][8];
    #pragma unroll
    for (int i = 0; i < 8; i++)
        #pragma unroll
        for (int j = 0; j < 8; j++) acc[i][j] = 0.f;

    for (int k0 = 0; k0 < K; k0 += 8) {
        // load A tile (M always multiple of 128 in our launches)
        float4 av = *(const float4*)(A + (size_t)(m0 + arow) * lda + k0 + ak);
        As[ak + 0][arow] = av.x;
        As[ak + 1][arow] = av.y;
        As[ak + 2][arow] = av.z;
        As[ak + 3][arow] = av.w;
        // load B tile with N guard
        int brow = n0 + arow;
        float4 bv = make_float4(0.f, 0.f, 0.f, 0.f);
        if (brow < N) bv = *(const float4*)(B + (size_t)brow * ldb + k0 + ak);
        Bs[ak + 0][arow] = bv.x;
        Bs[ak + 1][arow] = bv.y;
        Bs[ak + 2][arow] = bv.z;
        Bs[ak + 3][arow] = bv.w;
        __syncthreads();
        #pragma unroll
        for (int kk = 0; kk < 8; kk++) {
            float4 a0 = *(const float4*)&As[kk][tm];
            float4 a1 = *(const float4*)&As[kk][tm + 4];
            float4 b0 = *(const float4*)&Bs[kk][tn];
            float4 b1 = *(const float4*)&Bs[kk][tn + 4];
            float ar[8] = {a0.x, a0.y, a0.z, a0.w, a1.x, a1.y, a1.z, a1.w};
            float br[8] = {b0.x, b0.y, b0.z, b0.w, b1.x, b1.y, b1.z, b1.w};
            #pragma unroll
            for (int i = 0; i < 8; i++)
                #pragma unroll
                for (int j = 0; j < 8; j++) acc[i][j] += ar[i] * br[j];
        }
        __syncthreads();
    }

    #pragma unroll
    for (int i = 0; i < 8; i++) {
        int m = m0 + tm + i;
        #pragma unroll
        for (int j = 0; j < 8; j++) {
            int n = n0 + tn + j;
            if (n >= N) continue;
            float v = acc[i][j] + bias[n];
            if (MODE == 1) {
                int b = m >> 8, s = (m & 255) + 1;
                C[((size_t)(b * SEQ + s)) * HID + n] = v + extra[s * HID + n];
            } else if (MODE == 2) {
                C[(size_t)m * ldc + n] = 0.5f * v * (1.0f + erff(v * 0.70710678118654752f));
            } else if (MODE == 3) {
                C[(size_t)m * ldc + n] += v;
            } else {
                C[(size_t)m * ldc + n] = v;
            }
        }
    }
}

// ---------------- attention scores: S = q @ k^T * scale ----------------
__global__ void scores_kernel() {
    __shared__ float Qs[32][65];
    __shared__ float Ks[32][65];
    int z = blockIdx.z;            // b*2+h
    int b = z >> 1, h = z & 1;
    int qt = blockIdx.y, kt = blockIdx.x;
    int t = threadIdx.x;
    int qbase = b * SEQ;
    for (int idx = t; idx < 2048; idx += 256) {
        int r = idx >> 6, d = idx & 63;
        int sq = qt * 32 + r;
        Qs[r][d] = (sq < SEQ) ? g_qkv[(size_t)(qbase + sq) * 384 + h * 64 + d] : 0.f;
        int sk = kt * 32 + r;
        Ks[r][d] = (sk < SEQ) ? g_qkv[(size_t)(qbase + sk) * 384 + 128 + h * 64 + d] : 0.f;
    }
    __syncthreads();
    int q = t & 31;
    int k4 = (t >> 5) << 2;
    float a0 = 0.f, a1 = 0.f, a2 = 0.f, a3 = 0.f;
    #pragma unroll
    for (int d = 0; d < 64; d++) {
        float qa = Qs[q][d];
        a0 += qa * Ks[k4 + 0][d];
        a1 += qa * Ks[k4 + 1][d];
        a2 += qa * Ks[k4 + 2][d];
        a3 += qa * Ks[k4 + 3][d];
    }
    int sq = qt * 32 + q;
    if (sq < SEQ) {
        size_t base = (size_t)z * (SEQ * SEQ) + (size_t)sq * SEQ;
        int sk = kt * 32 + k4;
        if (sk + 0 < SEQ) g_attn[base + sk + 0] = a0 * SCALE_ATT;
        if (sk + 1 < SEQ) g_attn[base + sk + 1] = a1 * SCALE_ATT;
        if (sk + 2 < SEQ) g_attn[base + sk + 2] = a2 * SCALE_ATT;
        if (sk + 3 < SEQ) g_attn[base + sk + 3] = a3 * SCALE_ATT;
    }
}

// ---------------- softmax over each 257-wide attn row (1 warp/row) --------
__global__ void softmax_attn_kernel() {
    int warp = threadIdx.x >> 5, lane = threadIdx.x & 31;
    int row = blockIdx.x * 8 + warp;
    if (row >= 512 * SEQ) return;
    float* rp = g_attn + (size_t)row * SEQ;
    float ev[9];
    float mx = -1e30f;
    #pragma unroll
    for (int i = 0; i < 9; i++) {
        int c = lane + i * 32;
        ev[i] = (c < SEQ) ? rp[c] : -1e30f;
        mx = fmaxf(mx, ev[i]);
    }
    #pragma unroll
    for (int o = 16; o; o >>= 1) mx = fmaxf(mx, __shfl_xor_sync(0xffffffffu, mx, o));
    float sum = 0.f;
    #pragma unroll
    for (int i = 0; i < 9; i++) {
        int c = lane + i * 32;
        ev[i] = (c < SEQ) ? expf(ev[i] - mx) : 0.f;
        sum += ev[i];
    }
    #pragma unroll
    for (int o = 16; o; o >>= 1) sum += __shfl_xor_sync(0xffffffffu, sum, o);
    float inv = 1.0f / sum;
    #pragma unroll
    for (int i = 0; i < 9; i++) {
        int c = lane + i * 32;
        if (c < SEQ) rp[c] = ev[i] * inv;
    }
}

// ---------------- O = attn @ v, accumulated into residual ----------------
__global__ void av_kernel() {
    __shared__ float As[32][33];
    __shared__ float Vs[32][65];
    int z = blockIdx.y;            // b*2+h
    int b = z >> 1, h = z & 1;
    int qt = blockIdx.x;
    int t = threadIdx.x;
    int q = t >> 3;
    int eg = (t & 7) << 3;
    float acc[8];
    #pragma unroll
    for (int j = 0; j < 8; j++) acc[j] = 0.f;

    for (int kc = 0; kc < SEQ; kc += 32) {
        for (int idx = t; idx < 1024; idx += 256) {
            int r = idx >> 5, c = idx & 31;
            int sq = qt * 32 + r, sk = kc + c;
            As[r][c] = (sq < SEQ && sk < SEQ)
                ? g_attn[(size_t)z * (SEQ * SEQ) + (size_t)sq * SEQ + sk] : 0.f;
        }
        for (int idx = t; idx < 2048; idx += 256) {
            int r = idx >> 6, d = idx & 63;
            int sk = kc + r;
            Vs[r][d] = (sk < SEQ) ? g_qkv[(size_t)(b * SEQ + sk) * 384 + 256 + h * 64 + d] : 0.f;
        }
        __syncthreads();
        #pragma unroll
        for (int kk = 0; kk < 32; kk++) {
            float a = As[q][kk];
            #pragma unroll
            for (int j = 0; j < 8; j++) acc[j] += a * Vs[kk][eg + j];
        }
        __syncthreads();
    }
    int sq = qt * 32 + q;
    if (sq < SEQ) {
        float* op = g_out + (size_t)(b * SEQ + sq) * HID + h * 64 + eg;
        #pragma unroll
        for (int j = 0; j < 8; j++) op[j] += acc[j];
    }
}

// ---------------- head softmax: d_out[b,:] = softmax(logits[b,:]) ---------
__global__ void head_softmax_kernel(float* __restrict__ out) {
    int b = blockIdx.x;
    int t = threadIdx.x;
    __shared__ float sh[256];
    const float* lp = g_logits + (size_t)b * OUTD;
    float mx = -1e30f;
    for (int c = t; c < OUTD; c += 256) mx = fmaxf(mx, lp[c]);
    sh[t] = mx; __syncthreads();
    for (int s = 128; s > 0; s >>= 1) { if (t < s) sh[t] = fmaxf(sh[t], sh[t + s]); __syncthreads(); }
    mx = sh[0]; __syncthreads();
    float sum = 0.f;
    for (int c = t; c < OUTD; c += 256) sum += expf(lp[c] - mx);
    sh[t] = sum; __syncthreads();
    for (int s = 128; s > 0; s >>= 1) { if (t < s) sh[t] += sh[t + s]; __syncthreads(); }
    float inv = 1.0f / sh[0];
    for (int c = t; c < OUTD; c += 256) out[(size_t)b * OUTD + c] = expf(lp[c] - mx) * inv;
}

// ---------------- host launcher ----------------
extern "C" void kernel_launch(void* const* d_in, const int* in_sizes, int n_in,
                              void* d_out, int out_size) {
    const float* images = (const float*)d_in[0];
    const float* mapW   = (const float*)d_in[1];
    const float* mapb   = (const float*)d_in[2];
    const float* cls    = (const float*)d_in[3];
    const float* qW     = (const float*)d_in[4];
    const float* qb     = (const float*)d_in[5];
    const float* kW     = (const float*)d_in[6];
    const float* kb     = (const float*)d_in[7];
    const float* vW     = (const float*)d_in[8];
    const float* vb     = (const float*)d_in[9];
    const float* ln1g   = (const float*)d_in[10];
    const float* ln1b   = (const float*)d_in[11];
    const float* ln2g   = (const float*)d_in[12];
    const float* ln2b   = (const float*)d_in[13];
    const float* w1     = (const float*)d_in[14];
    const float* b1     = (const float*)d_in[15];
    const float* w2     = (const float*)d_in[16];
    const float* b2     = (const float*)d_in[17];
    const float* headW  = (const float*)d_in[18];
    const float* headb  = (const float*)d_in[19];
    float* out = (float*)d_out;

    float *pX0, *pWp, *pOut, *pX, *pQkv, *pMlp, *pLog, *pPos, *pWq, *pBq;
    cudaGetSymbolAddress((void**)&pX0,  g_X0);
    cudaGetSymbolAddress((void**)&pWp,  g_mapWp);
    cudaGetSymbolAddress((void**)&pOut, g_out);
    cudaGetSymbolAddress((void**)&pX,   g_x);
    cudaGetSymbolAddress((void**)&pQkv, g_qkv);
    cudaGetSymbolAddress((void**)&pMlp, g_mlp);
    cudaGetSymbolAddress((void**)&pLog, g_logits);
    cudaGetSymbolAddress((void**)&pPos, g_pos);
    cudaGetSymbolAddress((void**)&pWq,  g_wqkv);
    cudaGetSymbolAddress((void**)&pBq,  g_bqkv);

    pos_kernel<<<(SEQ * HID + 255) / 256, 256>>>();
    gather_kernel<<<(TROWS * KPAD) / 256, 256>>>(images);
    padw_kernel<<<(HID * KPAD + 255) / 256, 256>>>(mapW);
    cls_kernel<<<(BATCHN * HID) / 256, 256>>>(cls);

    // patch embed: tokens = X0 @ mapWp^T + mapb + POS, scattered into g_out
    sgemm_kernel<1><<<dim3(1, TROWS / 128), 256>>>(
        pX0, KPAD, pWp, KPAD, pOut, HID, TROWS, HID, KPAD, mapb, pPos);

    for (int blk = 0; blk < 2; blk++) {
        ln_kernel<<<ROWS / 8, 256>>>(pOut, pX, ln1g + blk * HID, ln1b + blk * HID);
        build_wqkv_kernel<<<(384 * HID + 255) / 256, 256>>>(blk, qW, qb, kW, kb, vW, vb);
        // qkv = x @ Wqkv^T + bqkv
        sgemm_kernel<0><<<dim3(3, ROWS / 128), 256>>>(
            pX, HID, pWq, HID, pQkv, 384, ROWS, 384, HID, pBq, nullptr);
        scores_kernel<<<dim3(9, 9, 512), 256>>>();
        softmax_attn_kernel<<<(512 * SEQ + 7) / 8, 256>>>();
        av_kernel<<<dim3(9, 512), 256>>>();
        ln_kernel<<<ROWS / 8, 256>>>(pOut, pX, ln2g + blk * HID, ln2b + blk * HID);
        // mlp1 with exact gelu
        sgemm_kernel<2><<<dim3(4, ROWS / 128), 256>>>(
            pX, HID, w1 + (size_t)blk * FF * HID, HID, pMlp, FF, ROWS, FF, HID,
            b1 + blk * FF, nullptr);
        // mlp2 + residual accumulate
        sgemm_kernel<3><<<dim3(1, ROWS / 128), 256>>>(
            pMlp, FF, w2 + (size_t)blk * HID * FF, FF, pOut, HID, ROWS, HID, FF,
            b2 + blk * HID, nullptr);
    }

    // head: logits = cls_rows(g_out) @ headW^T + headb   (A rows strided by SEQ*HID)
    sgemm_kernel<4><<<dim3(8, 2), 256>>>(
        pOut, SEQ * HID, headW, HID, pLog, OUTD, BATCHN, OUTD, HID, headb, nullptr);
    head_softmax_kernel<<<BATCHN, 256>>>(out);
}

// round 4
// speedup vs baseline: 1.3678x; 1.3678x over previous
#include <cuda_runtime.h>
#include <math.h>

// ---------------- problem constants ----------------
#define BATCHN   256
#define SEQ      257
#define HID      128
#define NPATCH   256
#define INPUT_D  588
#define KPAD     592
#define FF       512
#define OUTD     1000
#define DH       64
#define ROWS     (BATCHN*SEQ)     // 65792 = 514*128
#define TROWS    (BATCHN*NPATCH)  // 65536 = 512*128
#define SCALE_ATT 0.125f

// ---------------- scratch ----------------
__device__ float g_X0[TROWS * KPAD];
__device__ float g_mapWp[HID * KPAD];
__device__ float g_out[ROWS * HID];
__device__ float g_x[ROWS * HID];
__device__ float g_qkv[ROWS * 384];
__device__ float g_mlp[ROWS * FF];
__device__ float g_logits[BATCHN * OUTD];
__device__ float g_pos[SEQ * HID];
__device__ float g_wqkvh[2 * 192 * 64];   // per-head fused q|k|v weight
__device__ float g_bqkvh[2 * 192];

// ---------------- positional embedding ----------------
__global__ void pos_kernel() {
    int idx = blockIdx.x * blockDim.x + threadIdx.x;
    if (idx >= SEQ * HID) return;
    int s = idx / HID, j = idx % HID;
    double e = (double)((j & 1) ? (j - 1) : j) / 128.0;
    double arg = (double)s / pow(10000.0, e);
    g_pos[idx] = (float)((j & 1) ? cos(arg) : sin(arg));
}

// ---------------- patch gather ----------------
__global__ void gather_kernel(const float* __restrict__ images) {
    int idx = blockIdx.x * blockDim.x + threadIdx.x;
    int r = idx / KPAD, k = idx - r * KPAD;
    float v = 0.f;
    if (k < INPUT_D) {
        int b = r >> 8, p = r & 255;
        int py = p >> 4, px = p & 15;
        int c = k / 196, rem = k - c * 196;
        int iy = rem / 14, ix = rem - iy * 14;
        v = images[((size_t)(b * 3 + c) * 224 + (py * 14 + iy)) * 224 + (px * 14 + ix)];
    }
    g_X0[idx] = v;
}

__global__ void padw_kernel(const float* __restrict__ mapW) {
    int idx = blockIdx.x * blockDim.x + threadIdx.x;
    if (idx >= HID * KPAD) return;
    int r = idx / KPAD, c = idx - r * KPAD;
    g_mapWp[idx] = (c < INPUT_D) ? mapW[r * INPUT_D + c] : 0.f;
}

__global__ void cls_kernel(const float* __restrict__ cls) {
    int idx = blockIdx.x * blockDim.x + threadIdx.x;
    if (idx >= BATCHN * HID) return;
    int b = idx >> 7, n = idx & 127;
    g_out[(size_t)b * SEQ * HID + n] = cls[n] + g_pos[n];
}

// ---------------- per-head fused qkv weight build ----------------
__global__ void build_wqkvh_kernel(int blk,
        const float* __restrict__ qW, const float* __restrict__ qb,
        const float* __restrict__ kW, const float* __restrict__ kb,
        const float* __restrict__ vW, const float* __restrict__ vb) {
    int idx = blockIdx.x * blockDim.x + threadIdx.x;
    if (idx >= 2 * 192 * 64) return;
    int h = idx / (192 * 64);
    int rem = idx - h * 192 * 64;
    int r = rem >> 6, d = rem & 63;
    int mat = r >> 6, e = r & 63;
    const float* W = (mat == 0) ? qW : (mat == 1) ? kW : vW;
    g_wqkvh[idx] = W[(((blk * 2 + h) * DH) + e) * DH + d];
    if (d == 0) {
        const float* B = (mat == 0) ? qb : (mat == 1) ? kb : vb;
        g_bqkvh[h * 192 + r] = B[(blk * 2 + h) * DH + e];
    }
}

// ---------------- layernorm ----------------
__global__ void ln_kernel(const float* __restrict__ src, float* __restrict__ dst,
                          const float* __restrict__ g, const float* __restrict__ bb) {
    int warp = threadIdx.x >> 5, lane = threadIdx.x & 31;
    int row = blockIdx.x * 8 + warp;
    if (row >= ROWS) return;
    float4 v = *(const float4*)(src + (size_t)row * HID + lane * 4);
    float s = v.x + v.y + v.z + v.w;
    #pragma unroll
    for (int o = 16; o; o >>= 1) s += __shfl_xor_sync(0xffffffffu, s, o);
    float mu = s * (1.0f / 128.0f);
    float dx = v.x - mu, dy = v.y - mu, dz = v.z - mu, dw = v.w - mu;
    float q = dx * dx + dy * dy + dz * dz + dw * dw;
    #pragma unroll
    for (int o = 16; o; o >>= 1) q += __shfl_xor_sync(0xffffffffu, q, o);
    float rs = rsqrtf(q * (1.0f / 128.0f) + 1e-5f);
    int n = lane * 4;
    float4 go = *(const float4*)(g + n);
    float4 bo = *(const float4*)(bb + n);
    float4 r;
    r.x = dx * rs * go.x + bo.x;
    r.y = dy * rs * go.y + bo.y;
    r.z = dz * rs * go.z + bo.z;
    r.w = dw * rs * go.w + bo.w;
    *(float4*)(dst + (size_t)row * HID + n) = r;
}

// ---------------- double-buffered SGEMM: C = A[M,K] @ B[N,K]^T ----------------
// MODE 0: C = acc + bias
// MODE 1: patch-embed scatter + pos
// MODE 2: gelu(acc + bias)
// MODE 3: C += acc + bias
// MODE 5: qkv per-head scatter: h = blockIdx.z; col = (n/64)*128 + h*64 + (n%64)
template <int MODE>
__global__ void __launch_bounds__(256, 2) sgemm_kernel(
    const float* __restrict__ A, int lda,
    const float* __restrict__ B, int ldb,
    float* __restrict__ C, int ldc,
    int M, int N, int K,
    const float* __restrict__ bias, const float* __restrict__ extra) {
    int hh = 0;
    if (MODE == 5) {
        hh = blockIdx.z;
        A += hh * 64;
        B += (size_t)hh * 192 * 64;
        bias += hh * 192;
    }
    __shared__ __align__(16) float As[2][8][128];
    __shared__ __align__(16) float Bs[2][8][128];
    int t = threadIdx.x;
    int n0 = blockIdx.x * 128;
    int m0 = blockIdx.y * 128;
    int arow = t >> 1;
    int ak = (t & 1) * 4;
    const float* Aptr = A + (size_t)(m0 + arow) * lda + ak;
    int brow = n0 + arow;
    const float* Bptr = B + (size_t)brow * ldb + ak;
    bool bvalid = brow < N;

    {
        float4 av = *(const float4*)Aptr;
        float4 bv = bvalid ? *(const float4*)Bptr : make_float4(0.f, 0.f, 0.f, 0.f);
        As[0][ak + 0][arow] = av.x; As[0][ak + 1][arow] = av.y;
        As[0][ak + 2][arow] = av.z; As[0][ak + 3][arow] = av.w;
        Bs[0][ak + 0][arow] = bv.x; Bs[0][ak + 1][arow] = bv.y;
        Bs[0][ak + 2][arow] = bv.z; Bs[0][ak + 3][arow] = bv.w;
    }
    __syncthreads();

    int tm = (t >> 4) << 3;
    int tn = (t & 15) << 3;
    float acc[8][8];
    #pragma unroll
    for (int i = 0; i < 8; i++)
        #pragma unroll
        for (int j = 0; j < 8; j++) acc[i][j] = 0.f;

    int ntiles = K >> 3;
    for (int it = 0; it < ntiles; ++it) {
        int cur = it & 1;
        float4 an, bn;
        bool more = (it + 1) < ntiles;
        if (more) {
            an = *(const float4*)(Aptr + (size_t)(it + 1) * 8);
            bn = bvalid ? *(const float4*)(Bptr + (size_t)(it + 1) * 8)
                        : make_float4(0.f, 0.f, 0.f, 0.f);
        }
        #pragma unroll
        for (int kk = 0; kk < 8; kk++) {
            float4 a0 = *(const float4*)&As[cur][kk][tm];
            float4 a1 = *(const float4*)&As[cur][kk][tm + 4];
            float4 b0 = *(const float4*)&Bs[cur][kk][tn];
            float4 b1 = *(const float4*)&Bs[cur][kk][tn + 4];
            float ar[8] = {a0.x, a0.y, a0.z, a0.w, a1.x, a1.y, a1.z, a1.w};
            float br[8] = {b0.x, b0.y, b0.z, b0.w, b1.x, b1.y, b1.z, b1.w};
            #pragma unroll
            for (int i = 0; i < 8; i++)
                #pragma unroll
                for (int j = 0; j < 8; j++) acc[i][j] += ar[i] * br[j];
        }
        if (more) {
            int nxt = cur ^ 1;
            As[nxt][ak + 0][arow] = an.x; As[nxt][ak + 1][arow] = an.y;
            As[nxt][ak + 2][arow] = an.z; As[nxt][ak + 3][arow] = an.w;
            Bs[nxt][ak + 0][arow] = bn.x; Bs[nxt][ak + 1][arow] = bn.y;
            Bs[nxt][ak + 2][arow] = bn.z; Bs[nxt][ak + 3][arow] = bn.w;
        }
        __syncthreads();
    }

    #pragma unroll
    for (int i = 0; i < 8; i++) {
        int m = m0 + tm + i;
        #pragma unroll
        for (int j = 0; j < 8; j++) {
            int n = n0 + tn + j;
            if (n >= N) continue;
            float v = acc[i][j] + bias[n];
            if (MODE == 1) {
                int b = m >> 8, s = (m & 255) + 1;
                C[((size_t)(b * SEQ + s)) * HID + n] = v + extra[s * HID + n];
            } else if (MODE == 2) {
                C[(size_t)m * ldc + n] = 0.5f * v * (1.0f + erff(v * 0.70710678118654752f));
            } else if (MODE == 3) {
                C[(size_t)m * ldc + n] += v;
            } else if (MODE == 5) {
                int col = ((n >> 6) << 7) + hh * 64 + (n & 63);
                C[(size_t)m * 384 + col] = v;
            } else {
                C[(size_t)m * ldc + n] = v;
            }
        }
    }
}

// ---------------- flash attention: static smem, online softmax ----------------
// One CTA per (b,h). 8 warps; warp w owns q rows 4w..4w+3 of a 32-row q tile.
// Lane owns key index (S phase) and d-pair 2*lane (O phase).
__global__ void __launch_bounds__(256) attn_kernel() {
    __shared__ __align__(16) float Qs[32][68];   // pitch 68: float4-aligned rows
    __shared__ __align__(16) float Ks[32][68];
    __shared__ __align__(16) float Vs[32][64];
    __shared__ float Ps[32][36];

    int z = blockIdx.x;          // b*2 + h
    int b = z >> 1, h = z & 1;
    int t = threadIdx.x;
    int lane = t & 31, warp = t >> 5;
    int q0 = warp * 4;
    size_t base = (size_t)b * SEQ * 384;

    for (int qt = 0; qt < 9; qt++) {
        // load Q tile (zero-fill OOB rows)
        for (int idx = t; idx < 2048; idx += 256) {
            int r = idx >> 6, d = idx & 63;
            int sq = qt * 32 + r;
            Qs[r][d] = (sq < SEQ) ? g_qkv[base + (size_t)sq * 384 + h * 64 + d] : 0.f;
        }
        float m[4], l[4], o0[4], o1[4];
        #pragma unroll
        for (int i = 0; i < 4; i++) { m[i] = -1e30f; l[i] = 0.f; o0[i] = 0.f; o1[i] = 0.f; }
        __syncthreads();

        for (int kc = 0; kc < 9; kc++) {
            // load K,V chunk (zero-fill OOB rows)
            for (int idx = t; idx < 2048; idx += 256) {
                int r = idx >> 6, d = idx & 63;
                int sk = kc * 32 + r;
                float kv = 0.f, vv = 0.f;
                if (sk < SEQ) {
                    kv = g_qkv[base + (size_t)sk * 384 + 128 + h * 64 + d];
                    vv = g_qkv[base + (size_t)sk * 384 + 256 + h * 64 + d];
                }
                Ks[r][d] = kv;
                Vs[r][d] = vv;
            }
            __syncthreads();

            // S[row][lane] = Q[row] . K[lane]
            float s[4] = {0.f, 0.f, 0.f, 0.f};
            #pragma unroll
            for (int d4 = 0; d4 < 64; d4 += 4) {
                float4 kv = *(const float4*)&Ks[lane][d4];
                float4 qa = *(const float4*)&Qs[q0 + 0][d4];
                float4 qb = *(const float4*)&Qs[q0 + 1][d4];
                float4 qc = *(const float4*)&Qs[q0 + 2][d4];
                float4 qd = *(const float4*)&Qs[q0 + 3][d4];
                s[0] += qa.x * kv.x + qa.y * kv.y + qa.z * kv.z + qa.w * kv.w;
                s[1] += qb.x * kv.x + qb.y * kv.y + qb.z * kv.z + qb.w * kv.w;
                s[2] += qc.x * kv.x + qc.y * kv.y + qc.z * kv.z + qc.w * kv.w;
                s[3] += qd.x * kv.x + qd.y * kv.y + qd.z * kv.z + qd.w * kv.w;
            }
            int sk = kc * 32 + lane;
            bool kval = sk < SEQ;

            // online softmax update per row
            #pragma unroll
            for (int i = 0; i < 4; i++) {
                float sv = kval ? s[i] * SCALE_ATT : -1e30f;
                float cm = sv;
                #pragma unroll
                for (int o = 16; o; o >>= 1) cm = fmaxf(cm, __shfl_xor_sync(0xffffffffu, cm, o));
                float mn = fmaxf(m[i], cm);
                float sc = expf(m[i] - mn);
                float p  = kval ? expf(sv - mn) : 0.f;
                float cs = p;
                #pragma unroll
                for (int o = 16; o; o >>= 1) cs += __shfl_xor_sync(0xffffffffu, cs, o);
                l[i] = l[i] * sc + cs;
                m[i] = mn;
                o0[i] *= sc; o1[i] *= sc;
                Ps[q0 + i][lane] = p;
            }
            __syncwarp();

            // O update: lane owns d = 2*lane, 2*lane+1
            #pragma unroll 8
            for (int k = 0; k < 32; k++) {
                float2 vv = *(const float2*)&Vs[k][2 * lane];
                float pa = Ps[q0 + 0][k];
                float pb = Ps[q0 + 1][k];
                float pc = Ps[q0 + 2][k];
                float pd = Ps[q0 + 3][k];
                o0[0] += pa * vv.x; o1[0] += pa * vv.y;
                o0[1] += pb * vv.x; o1[1] += pb * vv.y;
                o0[2] += pc * vv.x; o1[2] += pc * vv.y;
                o0[3] += pd * vv.x; o1[3] += pd * vv.y;
            }
            __syncthreads();
        }

        // epilogue: normalize, accumulate into residual
        #pragma unroll
        for (int i = 0; i < 4; i++) {
            int gq = qt * 32 + q0 + i;
            if (gq < SEQ) {
                float inv = 1.0f / l[i];
                float* op = g_out + ((size_t)(b * SEQ + gq)) * HID + h * 64 + 2 * lane;
                op[0] += o0[i] * inv;
                op[1] += o1[i] * inv;
            }
        }
        __syncthreads();
    }
}

// ---------------- head softmax ----------------
__global__ void head_softmax_kernel(float* __restrict__ out) {
    int b = blockIdx.x;
    int t = threadIdx.x;
    __shared__ float sh[256];
    const float* lp = g_logits + (size_t)b * OUTD;
    float mx = -1e30f;
    for (int c = t; c < OUTD; c += 256) mx = fmaxf(mx, lp[c]);
    sh[t] = mx; __syncthreads();
    for (int s = 128; s > 0; s >>= 1) { if (t < s) sh[t] = fmaxf(sh[t], sh[t + s]); __syncthreads(); }
    mx = sh[0]; __syncthreads();
    float sum = 0.f;
    for (int c = t; c < OUTD; c += 256) sum += expf(lp[c] - mx);
    sh[t] = sum; __syncthreads();
    for (int s = 128; s > 0; s >>= 1) { if (t < s) sh[t] += sh[t + s]; __syncthreads(); }
    float inv = 1.0f / sh[0];
    for (int c = t; c < OUTD; c += 256) out[(size_t)b * OUTD + c] = expf(lp[c] - mx) * inv;
}

// ---------------- host launcher ----------------
extern "C" void kernel_launch(void* const* d_in, const int* in_sizes, int n_in,
                              void* d_out, int out_size) {
    const float* images = (const float*)d_in[0];
    const float* mapW   = (const float*)d_in[1];
    const float* mapb   = (const float*)d_in[2];
    const float* cls    = (const float*)d_in[3];
    const float* qW     = (const float*)d_in[4];
    const float* qb     = (const float*)d_in[5];
    const float* kW     = (const float*)d_in[6];
    const float* kb     = (const float*)d_in[7];
    const float* vW     = (const float*)d_in[8];
    const float* vb     = (const float*)d_in[9];
    const float* ln1g   = (const float*)d_in[10];
    const float* ln1b   = (const float*)d_in[11];
    const float* ln2g   = (const float*)d_in[12];
    const float* ln2b   = (const float*)d_in[13];
    const float* w1     = (const float*)d_in[14];
    const float* b1     = (const float*)d_in[15];
    const float* w2     = (const float*)d_in[16];
    const float* b2     = (const float*)d_in[17];
    const float* headW  = (const float*)d_in[18];
    const float* headb  = (const float*)d_in[19];
    float* out = (float*)d_out;

    float *pX0, *pWp, *pOut, *pX, *pQkv, *pMlp, *pLog, *pPos, *pWq, *pBq;
    cudaGetSymbolAddress((void**)&pX0,  g_X0);
    cudaGetSymbolAddress((void**)&pWp,  g_mapWp);
    cudaGetSymbolAddress((void**)&pOut, g_out);
    cudaGetSymbolAddress((void**)&pX,   g_x);
    cudaGetSymbolAddress((void**)&pQkv, g_qkv);
    cudaGetSymbolAddress((void**)&pMlp, g_mlp);
    cudaGetSymbolAddress((void**)&pLog, g_logits);
    cudaGetSymbolAddress((void**)&pPos, g_pos);
    cudaGetSymbolAddress((void**)&pWq,  g_wqkvh);
    cudaGetSymbolAddress((void**)&pBq,  g_bqkvh);

    pos_kernel<<<(SEQ * HID + 255) / 256, 256>>>();
    gather_kernel<<<(TROWS * KPAD) / 256, 256>>>(images);
    padw_kernel<<<(HID * KPAD + 255) / 256, 256>>>(mapW);
    cls_kernel<<<(BATCHN * HID) / 256, 256>>>(cls);

    sgemm_kernel<1><<<dim3(1, TROWS / 128), 256>>>(
        pX0, KPAD, pWp, KPAD, pOut, HID, TROWS, HID, KPAD, mapb, pPos);

    for (int blk = 0; blk < 2; blk++) {
        ln_kernel<<<ROWS / 8, 256>>>(pOut, pX, ln1g + blk * HID, ln1b + blk * HID);
        build_wqkvh_kernel<<<(2 * 192 * 64 + 255) / 256, 256>>>(blk, qW, qb, kW, kb, vW, vb);
        sgemm_kernel<5><<<dim3(2, ROWS / 128, 2), 256>>>(
            pX, HID, pWq, 64, pQkv, 384, ROWS, 192, 64, pBq, nullptr);
        attn_kernel<<<512, 256>>>();
        ln_kernel<<<ROWS / 8, 256>>>(pOut, pX, ln2g + blk * HID, ln2b + blk * HID);
        sgemm_kernel<2><<<dim3(4, ROWS / 128), 256>>>(
            pX, HID, w1 + (size_t)blk * FF * HID, HID, pMlp, FF, ROWS, FF, HID,
            b1 + blk * FF, nullptr);
        sgemm_kernel<3><<<dim3(1, ROWS / 128), 256>>>(
            pMlp, FF, w2 + (size_t)blk * HID * FF, FF, pOut, HID, ROWS, HID, FF,
            b2 + blk * HID, nullptr);
    }

    sgemm_kernel<0><<<dim3(8, 2), 256>>>(
        pOut, SEQ * HID, headW, HID, pLog, OUTD, BATCHN, OUTD, HID, headb, nullptr);
    head_softmax_kernel<<<BATCHN, 256>>>(out);
}

// round 5
// speedup vs baseline: 1.6758x; 1.2252x over previous
#include <cuda_runtime.h>
#include <mma.h>
#include <math.h>

using namespace nvcuda;

// ---------------- problem constants ----------------
#define BATCHN   256
#define SEQ      257
#define HID      128
#define NPATCH   256
#define INPUT_D  588
#define KPAD     608              // padded to multiple of 32 for tf32 GEMM
#define FF       512
#define OUTD     1000
#define DH       64
#define ROWS     (BATCHN*SEQ)     // 65792 = 514*128
#define TROWS    (BATCHN*NPATCH)  // 65536 = 512*128
#define SCALE_ATT 0.125f

// ---------------- scratch ----------------
__device__ float g_X0[TROWS * KPAD];
__device__ float g_mapWp[HID * KPAD];
__device__ float g_out[ROWS * HID];
__device__ float g_x[ROWS * HID];
__device__ float g_qkv[ROWS * 384];
__device__ float g_mlp[ROWS * FF];
__device__ float g_logits[BATCHN * OUTD];
__device__ float g_pos[SEQ * HID];
__device__ float g_wqkvh[2 * 192 * 64];
__device__ float g_bqkvh[2 * 192];

// ---------------- positional embedding ----------------
__global__ void pos_kernel() {
    int idx = blockIdx.x * blockDim.x + threadIdx.x;
    if (idx >= SEQ * HID) return;
    int s = idx / HID, j = idx % HID;
    double e = (double)((j & 1) ? (j - 1) : j) / 128.0;
    double arg = (double)s / pow(10000.0, e);
    g_pos[idx] = (float)((j & 1) ? cos(arg) : sin(arg));
}

// ---------------- patch gather ----------------
__global__ void gather_kernel(const float* __restrict__ images) {
    int idx = blockIdx.x * blockDim.x + threadIdx.x;
    int r = idx / KPAD, k = idx - r * KPAD;
    float v = 0.f;
    if (k < INPUT_D) {
        int b = r >> 8, p = r & 255;
        int py = p >> 4, px = p & 15;
        int c = k / 196, rem = k - c * 196;
        int iy = rem / 14, ix = rem - iy * 14;
        v = images[((size_t)(b * 3 + c) * 224 + (py * 14 + iy)) * 224 + (px * 14 + ix)];
    }
    g_X0[idx] = v;
}

__global__ void padw_kernel(const float* __restrict__ mapW) {
    int idx = blockIdx.x * blockDim.x + threadIdx.x;
    if (idx >= HID * KPAD) return;
    int r = idx / KPAD, c = idx - r * KPAD;
    g_mapWp[idx] = (c < INPUT_D) ? mapW[r * INPUT_D + c] : 0.f;
}

__global__ void cls_kernel(const float* __restrict__ cls) {
    int idx = blockIdx.x * blockDim.x + threadIdx.x;
    if (idx >= BATCHN * HID) return;
    int b = idx >> 7, n = idx & 127;
    g_out[(size_t)b * SEQ * HID + n] = cls[n] + g_pos[n];
}

// ---------------- per-head fused qkv weight build ----------------
__global__ void build_wqkvh_kernel(int blk,
        const float* __restrict__ qW, const float* __restrict__ qb,
        const float* __restrict__ kW, const float* __restrict__ kb,
        const float* __restrict__ vW, const float* __restrict__ vb) {
    int idx = blockIdx.x * blockDim.x + threadIdx.x;
    if (idx >= 2 * 192 * 64) return;
    int h = idx / (192 * 64);
    int rem = idx - h * 192 * 64;
    int r = rem >> 6, d = rem & 63;
    int mat = r >> 6, e = r & 63;
    const float* W = (mat == 0) ? qW : (mat == 1) ? kW : vW;
    g_wqkvh[idx] = W[(((blk * 2 + h) * DH) + e) * DH + d];
    if (d == 0) {
        const float* B = (mat == 0) ? qb : (mat == 1) ? kb : vb;
        g_bqkvh[h * 192 + r] = B[(blk * 2 + h) * DH + e];
    }
}

// ---------------- layernorm ----------------
__global__ void ln_kernel(const float* __restrict__ src, float* __restrict__ dst,
                          const float* __restrict__ g, const float* __restrict__ bb) {
    int warp = threadIdx.x >> 5, lane = threadIdx.x & 31;
    int row = blockIdx.x * 8 + warp;
    if (row >= ROWS) return;
    float4 v = *(const float4*)(src + (size_t)row * HID + lane * 4);
    float s = v.x + v.y + v.z + v.w;
    #pragma unroll
    for (int o = 16; o; o >>= 1) s += __shfl_xor_sync(0xffffffffu, s, o);
    float mu = s * (1.0f / 128.0f);
    float dx = v.x - mu, dy = v.y - mu, dz = v.z - mu, dw = v.w - mu;
    float q = dx * dx + dy * dy + dz * dz + dw * dw;
    #pragma unroll
    for (int o = 16; o; o >>= 1) q += __shfl_xor_sync(0xffffffffu, q, o);
    float rs = rsqrtf(q * (1.0f / 128.0f) + 1e-5f);
    int n = lane * 4;
    float4 go = *(const float4*)(g + n);
    float4 bo = *(const float4*)(bb + n);
    float4 r;
    r.x = dx * rs * go.x + bo.x;
    r.y = dy * rs * go.y + bo.y;
    r.z = dz * rs * go.z + bo.z;
    r.w = dw * rs * go.w + bo.w;
    *(float4*)(dst + (size_t)row * HID + n) = r;
}

// ---------------- tf32 tensor-core GEMM: C = A[M,K] @ B[N,K]^T ----------------
// Block tile 128x64, 8 warps (4x2), each warp 32x32 (2x2 wmma m16n16k8 frags).
// Requires: M % 128 == 0, N % 64 == 0, K % 32 == 0. All launches satisfy this.
// MODE 0: C = acc + bias
// MODE 1: patch-embed scatter + pos
// MODE 2: gelu(acc + bias)
// MODE 3: C += acc + bias
// MODE 5: qkv per-head scatter: h = blockIdx.z; col = (n/64)*128 + h*64 + (n%64)
#define TG_AB_PITCH 40
#define TG_C_PITCH  68
template <int MODE>
__global__ void __launch_bounds__(256) tgemm_kernel(
    const float* __restrict__ A, int lda,
    const float* __restrict__ B, int ldb,
    float* __restrict__ C, int ldc,
    int M, int N, int K,
    const float* __restrict__ bias, const float* __restrict__ extra) {
    int hh = 0;
    if (MODE == 5) {
        hh = blockIdx.z;
        A += hh * 64;
        B += (size_t)hh * 192 * 64;
        bias += hh * 192;
    }
    __shared__ __align__(16) float smraw[128 * TG_C_PITCH];  // 34816 B
    float (*As)[TG_AB_PITCH] = (float(*)[TG_AB_PITCH])smraw;
    float (*Bs)[TG_AB_PITCH] = (float(*)[TG_AB_PITCH])(smraw + 128 * TG_AB_PITCH);
    float (*Cs)[TG_C_PITCH]  = (float(*)[TG_C_PITCH])smraw;

    int t = threadIdx.x;
    int warp = t >> 5;
    int wm = warp >> 1, wn = warp & 1;
    int m0 = blockIdx.y * 128, n0 = blockIdx.x * 64;

    wmma::fragment<wmma::accumulator, 16, 16, 8, float> acc[2][2];
    #pragma unroll
    for (int i = 0; i < 2; i++)
        #pragma unroll
        for (int j = 0; j < 2; j++) wmma::fill_fragment(acc[i][j], 0.f);

    int ar = t >> 1, ah = (t & 1) * 16;
    const float* Ap = A + (size_t)(m0 + ar) * lda + ah;
    const float* Bp = B + (size_t)(n0 + (t >> 1)) * ldb + ah;

    for (int k0 = 0; k0 < K; k0 += 32) {
        // load A tile 128x32
        {
            float4 v0 = *(const float4*)(Ap + k0);
            float4 v1 = *(const float4*)(Ap + k0 + 4);
            float4 v2 = *(const float4*)(Ap + k0 + 8);
            float4 v3 = *(const float4*)(Ap + k0 + 12);
            *(float4*)&As[ar][ah + 0]  = v0;
            *(float4*)&As[ar][ah + 4]  = v1;
            *(float4*)&As[ar][ah + 8]  = v2;
            *(float4*)&As[ar][ah + 12] = v3;
        }
        // load B tile 64x32 (threads 0..127)
        if (t < 128) {
            float4 v0 = *(const float4*)(Bp + k0);
            float4 v1 = *(const float4*)(Bp + k0 + 4);
            float4 v2 = *(const float4*)(Bp + k0 + 8);
            float4 v3 = *(const float4*)(Bp + k0 + 12);
            int br = t >> 1;
            *(float4*)&Bs[br][ah + 0]  = v0;
            *(float4*)&Bs[br][ah + 4]  = v1;
            *(float4*)&Bs[br][ah + 8]  = v2;
            *(float4*)&Bs[br][ah + 12] = v3;
        }
        __syncthreads();

        #pragma unroll
        for (int kk = 0; kk < 32; kk += 8) {
            wmma::fragment<wmma::matrix_a, 16, 16, 8, wmma::precision::tf32, wmma::row_major> af[2];
            wmma::fragment<wmma::matrix_b, 16, 16, 8, wmma::precision::tf32, wmma::col_major> bf[2];
            wmma::load_matrix_sync(af[0], &As[wm * 32 +  0][kk], TG_AB_PITCH);
            wmma::load_matrix_sync(af[1], &As[wm * 32 + 16][kk], TG_AB_PITCH);
            wmma::load_matrix_sync(bf[0], &Bs[wn * 32 +  0][kk], TG_AB_PITCH);
            wmma::load_matrix_sync(bf[1], &Bs[wn * 32 + 16][kk], TG_AB_PITCH);
            #pragma unroll
            for (int e = 0; e < af[0].num_elements; e++) {
                af[0].x[e] = wmma::__float_to_tf32(af[0].x[e]);
                af[1].x[e] = wmma::__float_to_tf32(af[1].x[e]);
            }
            #pragma unroll
            for (int e = 0; e < bf[0].num_elements; e++) {
                bf[0].x[e] = wmma::__float_to_tf32(bf[0].x[e]);
                bf[1].x[e] = wmma::__float_to_tf32(bf[1].x[e]);
            }
            #pragma unroll
            for (int i = 0; i < 2; i++)
                #pragma unroll
                for (int j = 0; j < 2; j++)
                    wmma::mma_sync(acc[i][j], af[i], bf[j], acc[i][j]);
        }
        __syncthreads();
    }

    // store accumulators to smem (C tile aliases A/B smem; synced above)
    #pragma unroll
    for (int i = 0; i < 2; i++)
        #pragma unroll
        for (int j = 0; j < 2; j++)
            wmma::store_matrix_sync(&Cs[wm * 32 + i * 16][wn * 32 + j * 16],
                                    acc[i][j], TG_C_PITCH, wmma::mem_row_major);
    __syncthreads();

    // epilogue
    for (int idx = t; idx < 128 * 64; idx += 256) {
        int r = idx >> 6, c = idx & 63;
        int m = m0 + r, n = n0 + c;
        float v = Cs[r][c] + bias[n];
        if (MODE == 1) {
            int b = m >> 8, s = (m & 255) + 1;
            C[((size_t)(b * SEQ + s)) * HID + n] = v + extra[s * HID + n];
        } else if (MODE == 2) {
            C[(size_t)m * ldc + n] = 0.5f * v * (1.0f + erff(v * 0.70710678118654752f));
        } else if (MODE == 3) {
            C[(size_t)m * ldc + n] += v;
        } else if (MODE == 5) {
            int col = ((n >> 6) << 7) + hh * 64 + (n & 63);
            C[(size_t)m * 384 + col] = v;
        } else {
            C[(size_t)m * ldc + n] = v;
        }
    }
}

// ---------------- fp32 SGEMM (kept for head: N=1000 with guards) ----------------
__global__ void __launch_bounds__(256, 2) sgemm_head_kernel(
    const float* __restrict__ A, int lda,
    const float* __restrict__ B, int ldb,
    float* __restrict__ C, int ldc,
    int M, int N, int K,
    const float* __restrict__ bias) {
    __shared__ __align__(16) float As[2][8][128];
    __shared__ __align__(16) float Bs[2][8][128];
    int t = threadIdx.x;
    int n0 = blockIdx.x * 128;
    int m0 = blockIdx.y * 128;
    int arow = t >> 1;
    int ak = (t & 1) * 4;
    const float* Aptr = A + (size_t)(m0 + arow) * lda + ak;
    int brow = n0 + arow;
    const float* Bptr = B + (size_t)brow * ldb + ak;
    bool bvalid = brow < N;

    {
        float4 av = *(const float4*)Aptr;
        float4 bv = bvalid ? *(const float4*)Bptr : make_float4(0.f, 0.f, 0.f, 0.f);
        As[0][ak + 0][arow] = av.x; As[0][ak + 1][arow] = av.y;
        As[0][ak + 2][arow] = av.z; As[0][ak + 3][arow] = av.w;
        Bs[0][ak + 0][arow] = bv.x; Bs[0][ak + 1][arow] = bv.y;
        Bs[0][ak + 2][arow] = bv.z; Bs[0][ak + 3][arow] = bv.w;
    }
    __syncthreads();

    int tm = (t >> 4) << 3;
    int tn = (t & 15) << 3;
    float acc[8][8];
    #pragma unroll
    for (int i = 0; i < 8; i++)
        #pragma unroll
        for (int j = 0; j < 8; j++) acc[i][j] = 0.f;

    int ntiles = K >> 3;
    for (int it = 0; it < ntiles; ++it) {
        int cur = it & 1;
        float4 an, bn;
        bool more = (it + 1) < ntiles;
        if (more) {
            an = *(const float4*)(Aptr + (size_t)(it + 1) * 8);
            bn = bvalid ? *(const float4*)(Bptr + (size_t)(it + 1) * 8)
                        : make_float4(0.f, 0.f, 0.f, 0.f);
        }
        #pragma unroll
        for (int kk = 0; kk < 8; kk++) {
            float4 a0 = *(const float4*)&As[cur][kk][tm];
            float4 a1 = *(const float4*)&As[cur][kk][tm + 4];
            float4 b0 = *(const float4*)&Bs[cur][kk][tn];
            float4 b1 = *(const float4*)&Bs[cur][kk][tn + 4];
            float ar[8] = {a0.x, a0.y, a0.z, a0.w, a1.x, a1.y, a1.z, a1.w};
            float br[8] = {b0.x, b0.y, b0.z, b0.w, b1.x, b1.y, b1.z, b1.w};
            #pragma unroll
            for (int i = 0; i < 8; i++)
                #pragma unroll
                for (int j = 0; j < 8; j++) acc[i][j] += ar[i] * br[j];
        }
        if (more) {
            int nxt = cur ^ 1;
            As[nxt][ak + 0][arow] = an.x; As[nxt][ak + 1][arow] = an.y;
            As[nxt][ak + 2][arow] = an.z; As[nxt][ak + 3][arow] = an.w;
            Bs[nxt][ak + 0][arow] = bn.x; Bs[nxt][ak + 1][arow] = bn.y;
            Bs[nxt][ak + 2][arow] = bn.z; Bs[nxt][ak + 3][arow] = bn.w;
        }
        __syncthreads();
    }

    #pragma unroll
    for (int i = 0; i < 8; i++) {
        int m = m0 + tm + i;
        #pragma unroll
        for (int j = 0; j < 8; j++) {
            int n = n0 + tn + j;
            if (n >= N) continue;
            C[(size_t)m * ldc + n] = acc[i][j] + bias[n];
        }
    }
}

// ---------------- flash attention (fp32, static smem, online softmax) ----------------
__global__ void __launch_bounds__(256) attn_kernel() {
    __shared__ __align__(16) float Qs[32][68];
    __shared__ __align__(16) float Ks[32][68];
    __shared__ __align__(16) float Vs[32][64];
    __shared__ float Ps[32][36];

    int z = blockIdx.x;
    int b = z >> 1, h = z & 1;
    int t = threadIdx.x;
    int lane = t & 31, warp = t >> 5;
    int q0 = warp * 4;
    size_t base = (size_t)b * SEQ * 384;

    for (int qt = 0; qt < 9; qt++) {
        for (int idx = t; idx < 2048; idx += 256) {
            int r = idx >> 6, d = idx & 63;
            int sq = qt * 32 + r;
            Qs[r][d] = (sq < SEQ) ? g_qkv[base + (size_t)sq * 384 + h * 64 + d] : 0.f;
        }
        float m[4], l[4], o0[4], o1[4];
        #pragma unroll
        for (int i = 0; i < 4; i++) { m[i] = -1e30f; l[i] = 0.f; o0[i] = 0.f; o1[i] = 0.f; }
        __syncthreads();

        for (int kc = 0; kc < 9; kc++) {
            for (int idx = t; idx < 2048; idx += 256) {
                int r = idx >> 6, d = idx & 63;
                int sk = kc * 32 + r;
                float kv = 0.f, vv = 0.f;
                if (sk < SEQ) {
                    kv = g_qkv[base + (size_t)sk * 384 + 128 + h * 64 + d];
                    vv = g_qkv[base + (size_t)sk * 384 + 256 + h * 64 + d];
                }
                Ks[r][d] = kv;
                Vs[r][d] = vv;
            }
            __syncthreads();

            float s[4] = {0.f, 0.f, 0.f, 0.f};
            #pragma unroll
            for (int d4 = 0; d4 < 64; d4 += 4) {
                float4 kv = *(const float4*)&Ks[lane][d4];
                float4 qa = *(const float4*)&Qs[q0 + 0][d4];
                float4 qb = *(const float4*)&Qs[q0 + 1][d4];
                float4 qc = *(const float4*)&Qs[q0 + 2][d4];
                float4 qd = *(const float4*)&Qs[q0 + 3][d4];
                s[0] += qa.x * kv.x + qa.y * kv.y + qa.z * kv.z + qa.w * kv.w;
                s[1] += qb.x * kv.x + qb.y * kv.y + qb.z * kv.z + qb.w * kv.w;
                s[2] += qc.x * kv.x + qc.y * kv.y + qc.z * kv.z + qc.w * kv.w;
                s[3] += qd.x * kv.x + qd.y * kv.y + qd.z * kv.z + qd.w * kv.w;
            }
            int sk = kc * 32 + lane;
            bool kval = sk < SEQ;

            #pragma unroll
            for (int i = 0; i < 4; i++) {
                float sv = kval ? s[i] * SCALE_ATT : -1e30f;
                float cm = sv;
                #pragma unroll
                for (int o = 16; o; o >>= 1) cm = fmaxf(cm, __shfl_xor_sync(0xffffffffu, cm, o));
                float mn = fmaxf(m[i], cm);
                float sc = expf(m[i] - mn);
                float p  = kval ? expf(sv - mn) : 0.f;
                float cs = p;
                #pragma unroll
                for (int o = 16; o; o >>= 1) cs += __shfl_xor_sync(0xffffffffu, cs, o);
                l[i] = l[i] * sc + cs;
                m[i] = mn;
                o0[i] *= sc; o1[i] *= sc;
                Ps[q0 + i][lane] = p;
            }
            __syncwarp();

            #pragma unroll 8
            for (int k = 0; k < 32; k++) {
                float2 vv = *(const float2*)&Vs[k][2 * lane];
                float pa = Ps[q0 + 0][k];
                float pb = Ps[q0 + 1][k];
                float pc = Ps[q0 + 2][k];
                float pd = Ps[q0 + 3][k];
                o0[0] += pa * vv.x; o1[0] += pa * vv.y;
                o0[1] += pb * vv.x; o1[1] += pb * vv.y;
                o0[2] += pc * vv.x; o1[2] += pc * vv.y;
                o0[3] += pd * vv.x; o1[3] += pd * vv.y;
            }
            __syncthreads();
        }

        #pragma unroll
        for (int i = 0; i < 4; i++) {
            int gq = qt * 32 + q0 + i;
            if (gq < SEQ) {
                float inv = 1.0f / l[i];
                float* op = g_out + ((size_t)(b * SEQ + gq)) * HID + h * 64 + 2 * lane;
                op[0] += o0[i] * inv;
                op[1] += o1[i] * inv;
            }
        }
        __syncthreads();
    }
}

// ---------------- head softmax ----------------
__global__ void head_softmax_kernel(float* __restrict__ out) {
    int b = blockIdx.x;
    int t = threadIdx.x;
    __shared__ float sh[256];
    const float* lp = g_logits + (size_t)b * OUTD;
    float mx = -1e30f;
    for (int c = t; c < OUTD; c += 256) mx = fmaxf(mx, lp[c]);
    sh[t] = mx; __syncthreads();
    for (int s = 128; s > 0; s >>= 1) { if (t < s) sh[t] = fmaxf(sh[t], sh[t + s]); __syncthreads(); }
    mx = sh[0]; __syncthreads();
    float sum = 0.f;
    for (int c = t; c < OUTD; c += 256) sum += expf(lp[c] - mx);
    sh[t] = sum; __syncthreads();
    for (int s = 128; s > 0; s >>= 1) { if (t < s) sh[t] += sh[t + s]; __syncthreads(); }
    float inv = 1.0f / sh[0];
    for (int c = t; c < OUTD; c += 256) out[(size_t)b * OUTD + c] = expf(lp[c] - mx) * inv;
}

// ---------------- host launcher ----------------
extern "C" void kernel_launch(void* const* d_in, const int* in_sizes, int n_in,
                              void* d_out, int out_size) {
    const float* images = (const float*)d_in[0];
    const float* mapW   = (const float*)d_in[1];
    const float* mapb   = (const float*)d_in[2];
    const float* cls    = (const float*)d_in[3];
    const float* qW     = (const float*)d_in[4];
    const float* qb     = (const float*)d_in[5];
    const float* kW     = (const float*)d_in[6];
    const float* kb     = (const float*)d_in[7];
    const float* vW     = (const float*)d_in[8];
    const float* vb     = (const float*)d_in[9];
    const float* ln1g   = (const float*)d_in[10];
    const float* ln1b   = (const float*)d_in[11];
    const float* ln2g   = (const float*)d_in[12];
    const float* ln2b   = (const float*)d_in[13];
    const float* w1     = (const float*)d_in[14];
    const float* b1     = (const float*)d_in[15];
    const float* w2     = (const float*)d_in[16];
    const float* b2     = (const float*)d_in[17];
    const float* headW  = (const float*)d_in[18];
    const float* headb  = (const float*)d_in[19];
    float* out = (float*)d_out;

    float *pX0, *pWp, *pOut, *pX, *pQkv, *pMlp, *pLog, *pPos, *pWq, *pBq;
    cudaGetSymbolAddress((void**)&pX0,  g_X0);
    cudaGetSymbolAddress((void**)&pWp,  g_mapWp);
    cudaGetSymbolAddress((void**)&pOut, g_out);
    cudaGetSymbolAddress((void**)&pX,   g_x);
    cudaGetSymbolAddress((void**)&pQkv, g_qkv);
    cudaGetSymbolAddress((void**)&pMlp, g_mlp);
    cudaGetSymbolAddress((void**)&pLog, g_logits);
    cudaGetSymbolAddress((void**)&pPos, g_pos);
    cudaGetSymbolAddress((void**)&pWq,  g_wqkvh);
    cudaGetSymbolAddress((void**)&pBq,  g_bqkvh);

    pos_kernel<<<(SEQ * HID + 255) / 256, 256>>>();
    gather_kernel<<<(TROWS * KPAD) / 256, 256>>>(images);
    padw_kernel<<<(HID * KPAD + 255) / 256, 256>>>(mapW);
    cls_kernel<<<(BATCHN * HID) / 256, 256>>>(cls);

    // patch embed: [65536,608] @ [128,608]^T -> scatter with pos
    tgemm_kernel<1><<<dim3(2, TROWS / 128), 256>>>(
        pX0, KPAD, pWp, KPAD, pOut, HID, TROWS, HID, KPAD, mapb, pPos);

    for (int blk = 0; blk < 2; blk++) {
        ln_kernel<<<ROWS / 8, 256>>>(pOut, pX, ln1g + blk * HID, ln1b + blk * HID);
        build_wqkvh_kernel<<<(2 * 192 * 64 + 255) / 256, 256>>>(blk, qW, qb, kW, kb, vW, vb);
        tgemm_kernel<5><<<dim3(3, ROWS / 128, 2), 256>>>(
            pX, HID, pWq, 64, pQkv, 384, ROWS, 192, 64, pBq, nullptr);
        attn_kernel<<<512, 256>>>();
        ln_kernel<<<ROWS / 8, 256>>>(pOut, pX, ln2g + blk * HID, ln2b + blk * HID);
        tgemm_kernel<2><<<dim3(8, ROWS / 128), 256>>>(
            pX, HID, w1 + (size_t)blk * FF * HID, HID, pMlp, FF, ROWS, FF, HID,
            b1 + blk * FF, nullptr);
        tgemm_kernel<3><<<dim3(2, ROWS / 128), 256>>>(
            pMlp, FF, w2 + (size_t)blk * HID * FF, FF, pOut, HID, ROWS, HID, FF,
            b2 + blk * HID, nullptr);
    }

    sgemm_head_kernel<<<dim3(8, 2), 256>>>(
        pOut, SEQ * HID, headW, HID, pLog, OUTD, BATCHN, OUTD, HID, headb);
    head_softmax_kernel<<<BATCHN, 256>>>(out);
}